// round 15
// baseline (speedup 1.0000x reference)
#include <cuda_runtime.h>
#include <cuda_bf16.h>
#include <cuda_fp16.h>
#include <math.h>

typedef unsigned int u32;
typedef unsigned long long u64;

#define BATCH 2
#define SEQ   2048
#define DIM   512
#define NHEAD 8
#define DK    64
#define MT    (BATCH*SEQ)
#define LOG2E 1.4426950408889634f
#define WSCALE 64.0f
#define INVWS  (1.0f/64.0f)

// ---------------- global scratch (alloc-free) ------------------------------
__device__ __half gXf[MT*DIM];                   // x as fp16
__device__ __half gW[4][DIM*DIM];                // W*64 fp16; 0..2 QKV contig, 3 = O
__device__ __half gQ[MT*DIM];                    // pre-scaled 0.125*log2e
__device__ __half gK[MT*DIM];
__device__ __half gV[MT*DIM];
__device__ __half gO[MT*DIM];                    // attn output, fp16
__device__ u32 g_mask[4*SEQ*(SEQ/32)];           // [b*2+par][row][word] compact bits

// ---------------- helpers ---------------------------------------------------
static __device__ __forceinline__ u32 smem_u32(const void* p) {
    u32 a; asm("{ .reg .u64 t; cvta.to.shared.u64 t, %1; cvt.u32.u64 %0, t; }" : "=r"(a) : "l"(p));
    return a;
}
// packs {lo, hi} halves
static __device__ __forceinline__ u32 cvtf16x2(float lo, float hi) {
    u32 d; asm("cvt.rn.f16x2.f32 %0, %1, %2;" : "=r"(d) : "f"(hi), "f"(lo)); return d;
}
static __device__ __forceinline__ u32 prmt0(u32 a, u32 sel) {
    u32 d; asm("prmt.b32 %0, %1, %2, %3;" : "=r"(d) : "r"(a), "r"(0u), "r"(sel)); return d;
}
static __device__ __forceinline__ u32 ex2h2(u32 x) {
    u32 d; asm("ex2.approx.f16x2 %0, %1;" : "=r"(d) : "r"(x)); return d;
}
static __device__ __forceinline__ u32 hadd2u(u32 a, u32 b) {
    u32 d; asm("add.f16x2 %0, %1, %2;" : "=r"(d) : "r"(a), "r"(b)); return d;
}
static __device__ __forceinline__ float h2sumf(u32 v) {
    float lo, hi;
    asm("{ .reg .f16 a, b; mov.b32 {a, b}, %2; cvt.f32.f16 %0, a; cvt.f32.f16 %1, b; }"
        : "=f"(lo), "=f"(hi) : "r"(v));
    return lo + hi;
}

#define LDM4(r0,r1,r2,r3,a) \
    asm volatile("ldmatrix.sync.aligned.m8n8.x4.shared.b16 {%0,%1,%2,%3}, [%4];" \
        : "=r"(r0),"=r"(r1),"=r"(r2),"=r"(r3) : "r"(a))
#define LDM4T(r0,r1,r2,r3,a) \
    asm volatile("ldmatrix.sync.aligned.m8n8.x4.trans.shared.b16 {%0,%1,%2,%3}, [%4];" \
        : "=r"(r0),"=r"(r1),"=r"(r2),"=r"(r3) : "r"(a))
#define MMAH(d,a,b) \
    asm volatile("mma.sync.aligned.m16n8k16.row.col.f32.f16.f16.f32 " \
        "{%0,%1,%2,%3}, {%4,%5,%6,%7}, {%8,%9}, {%0,%1,%2,%3};" \
        : "+f"((d)[0]),"+f"((d)[1]),"+f"((d)[2]),"+f"((d)[3]) \
        : "r"((a)[0]),"r"((a)[1]),"r"((a)[2]),"r"((a)[3]),"r"((b)[0]),"r"((b)[1]))

#define CPA16(d, s) asm volatile("cp.async.cg.shared.global [%0], [%1], 16;" :: "r"(d), "l"(s) : "memory")
#define CPCOMMIT()  asm volatile("cp.async.commit_group;" ::: "memory")
#define CPWAIT(n)   asm volatile("cp.async.wait_group %0;" :: "n"(n) : "memory")

// ---------------- fused prep: x->fp16, W*64->fp16, mask bit tables ----------
// blocks [0,2048): x conv; [2048,3072): W conv; [3072,5120): mask rows.
__global__ void prep_all(const float* __restrict__ x,
                         const float* __restrict__ Wq, const float* __restrict__ Wk,
                         const float* __restrict__ Wv, const float* __restrict__ Wo,
                         const int* __restrict__ seq_mask,
                         const int* __restrict__ sparse_masks) {
    int blk = blockIdx.x;
    if (blk < 2048) {                      // x: 2M elements, single fp16
        int i = (blk * 256 + threadIdx.x) * 4;
        float4 v = *(const float4*)(x + i);
        *(uint2*)(gXf + i) = make_uint2(cvtf16x2(v.x, v.y), cvtf16x2(v.z, v.w));
    } else if (blk < 3072) {               // weights: 256 blocks each, *64 single fp16
        int sel = (blk - 2048) >> 8, b2 = (blk - 2048) & 255;
        const float* src = sel == 0 ? Wq : sel == 1 ? Wk : sel == 2 ? Wv : Wo;
        int i = (b2 * 256 + threadIdx.x) * 4;
        float4 v = *(const float4*)(src + i);
        *(uint2*)(gW[sel] + i) = make_uint2(cvtf16x2(v.x*WSCALE, v.y*WSCALE),
                                            cvtf16x2(v.z*WSCALE, v.w*WSCALE));
    } else {                               // mask rows
        int row  = blk - 3072;
        int warp = threadIdx.x >> 5, lane = threadIdx.x & 31;
        const int* s0 = seq_mask     + (size_t)0*SEQ*SEQ + (size_t)row*SEQ;
        const int* s1 = seq_mask     + (size_t)1*SEQ*SEQ + (size_t)row*SEQ;
        const int* p0 = sparse_masks + (size_t)0*SEQ*SEQ + (size_t)row*SEQ;
        const int* p1 = sparse_masks + (size_t)1*SEQ*SEQ + (size_t)row*SEQ;
        int a0[8], a1[8], b0[8], b1[8];
        #pragma unroll
        for (int q = 0; q < 8; q++) {
            int j = (warp*8 + q)*32 + lane;
            a0[q] = s0[j]; a1[q] = s1[j]; b0[q] = p0[j]; b1[q] = p1[j];
        }
        #pragma unroll
        for (int q = 0; q < 8; q++) {
            int w = warp*8 + q;
            u32 m00 = __ballot_sync(0xffffffffu, (a0[q] & b0[q]) != 0);
            u32 m01 = __ballot_sync(0xffffffffu, (a0[q] & b1[q]) != 0);
            u32 m10 = __ballot_sync(0xffffffffu, (a1[q] & b0[q]) != 0);
            u32 m11 = __ballot_sync(0xffffffffu, (a1[q] & b1[q]) != 0);
            if (lane == 0) {
                g_mask[((size_t)0*SEQ + row)*(SEQ/32) + w] = m00;
                g_mask[((size_t)1*SEQ + row)*(SEQ/32) + w] = m01;
                g_mask[((size_t)2*SEQ + row)*(SEQ/32) + w] = m10;
                g_mask[((size_t)3*SEQ + row)*(SEQ/32) + w] = m11;
            }
        }
    }
}

// ---------------- QKV GEMM: 64x128 tile (A = x fp16, B = QKV*64 fp16) -------
// Stage (24KB): A 64x128B @0 (8KB), B 128x128B @8192 (16KB).
#define PJ_BUF 24576
__global__ __launch_bounds__(256, 3) void proj_gemm() {
    extern __shared__ char dsm[];
    u32 sb = (smem_u32(dsm) + 127) & ~127u;

    const __half* A_f = gXf;
    const __half* B_f = gW[0];

    int tid = threadIdx.x, lane = tid & 31, warp = tid >> 5;
    int t4 = lane & 3, t8 = lane >> 2;
    int mrl = lane & 7, mm = lane >> 3;
    int wm = warp & 1, wn = warp >> 1;            // 2 x 4 warps, warp tile 32x32
    int m0 = blockIdx.x * 64, n0 = blockIdx.y * 128;

    #define PJ_ISSUE(c, buf) do { \
        _Pragma("unroll") \
        for (int q = 0; q < 6; q++) { \
            int idx = tid + q*256; \
            const __half* s; u32 d; \
            if (idx < 512) { \
                int r = idx >> 3, ch = idx & 7; \
                s = A_f + (size_t)(m0 + r)*DIM + (c)*64 + ch*8; \
                d = sb + (buf)*PJ_BUF + r*128 + ((ch ^ (r & 7)) << 4); \
            } else { \
                int i2 = idx - 512; \
                int r = i2 >> 3, ch = i2 & 7; \
                s = B_f + (size_t)(n0 + r)*DIM + (c)*64 + ch*8; \
                d = sb + (buf)*PJ_BUF + 8192 + r*128 + ((ch ^ (r & 7)) << 4); \
            } \
            CPA16(d, s); \
        } \
        CPCOMMIT(); \
    } while (0)

    float C[2][4][4];
    #pragma unroll
    for (int a = 0; a < 2; a++)
        #pragma unroll
        for (int b = 0; b < 4; b++)
            #pragma unroll
            for (int c = 0; c < 4; c++) C[a][b][c] = 0.f;

    PJ_ISSUE(0, 0);
    PJ_ISSUE(1, 1);

    for (int c = 0; c < 8; c++) {
        if (c < 7) CPWAIT(1); else CPWAIT(0);
        __syncthreads();
        u32 bb = sb + (c & 1)*PJ_BUF;

        #pragma unroll
        for (int ks = 0; ks < 4; ks++) {
            u32 AF[2][4], BF[4][2];
            int ch = 2*ks + (mm >> 1);
            #pragma unroll
            for (int fm = 0; fm < 2; fm++) {
                int row = wm*32 + fm*16 + (mm & 1)*8 + mrl;
                u32 a = bb + row*128 + ((ch ^ (row & 7)) << 4);
                LDM4(AF[fm][0], AF[fm][1], AF[fm][2], AF[fm][3], a);
            }
            #pragma unroll
            for (int p = 0; p < 2; p++) {
                int row = wn*32 + p*16 + (mm & 1)*8 + mrl;
                u32 a = bb + 8192 + row*128 + ((ch ^ (row & 7)) << 4);
                LDM4(BF[2*p][0], BF[2*p+1][0], BF[2*p][1], BF[2*p+1][1], a);
            }
            #pragma unroll
            for (int fm = 0; fm < 2; fm++)
                #pragma unroll
                for (int fn = 0; fn < 4; fn++)
                    MMAH(C[fm][fn], AF[fm], BF[fn]);
        }
        __syncthreads();
        if (c + 2 < 8) PJ_ISSUE(c + 2, c & 1);
    }

    #pragma unroll
    for (int fm = 0; fm < 2; fm++) {
        int rA = m0 + wm*32 + fm*16 + t8;
        #pragma unroll
        for (int fn = 0; fn < 4; fn++) {
            int n = n0 + wn*32 + fn*8 + 2*t4;
            float c0 = C[fm][fn][0], c1 = C[fm][fn][1];
            float c2 = C[fm][fn][2], c3 = C[fm][fn][3];
            int osel = n >> 9, col = n & 511;
            __half* dst = osel == 0 ? gQ : osel == 1 ? gK : gV;
            float sc = (osel == 0) ? 0.125f * LOG2E * INVWS : INVWS;
            *(u32*)(dst + (size_t)rA*DIM + col)     = cvtf16x2(c0*sc, c1*sc);
            *(u32*)(dst + (size_t)(rA+8)*DIM + col) = cvtf16x2(c2*sc, c3*sc);
        }
    }
}

// ---------------- O-projection: 64x64 tile, 4 CTAs/SM -----------------------
// A = gO fp16, B = Wo*64 fp16 -> fp32 out (/64). Stage 16KB (A 8KB, B 8KB).
#define OP_BUF 16384
__global__ __launch_bounds__(256, 4) void oproj_gemm(float* __restrict__ Yout) {
    extern __shared__ char dsm[];
    u32 sb = (smem_u32(dsm) + 127) & ~127u;

    int tid = threadIdx.x, lane = tid & 31, warp = tid >> 5;
    int t4 = lane & 3, t8 = lane >> 2;
    int mrl = lane & 7, mm = lane >> 3;
    int wm = warp & 1, wn = warp >> 1;            // 2 x 4 warps, warp tile 32x16
    int m0 = blockIdx.x * 64, n0 = blockIdx.y * 64;

    // per buffer: A 512 + B 512 = 1024 16B-copies; 4 per thread
    #define OP_ISSUE(c, buf) do { \
        _Pragma("unroll") \
        for (int q = 0; q < 4; q++) { \
            int idx = tid + q*256; \
            int mtx = idx >> 9, rem = idx & 511, r = rem >> 3, ch = rem & 7; \
            const __half* s = (mtx ? gW[3] + (size_t)(n0 + r)*DIM \
                                   : gO    + (size_t)(m0 + r)*DIM) + (c)*64 + ch*8; \
            u32 d = sb + (buf)*OP_BUF + mtx*8192 + r*128 + ((ch ^ (r & 7)) << 4); \
            CPA16(d, s); \
        } \
        CPCOMMIT(); \
    } while (0)

    float C[2][2][4];
    #pragma unroll
    for (int a = 0; a < 2; a++)
        #pragma unroll
        for (int b = 0; b < 2; b++)
            #pragma unroll
            for (int c = 0; c < 4; c++) C[a][b][c] = 0.f;

    OP_ISSUE(0, 0);
    OP_ISSUE(1, 1);

    for (int c = 0; c < 8; c++) {
        if (c < 7) CPWAIT(1); else CPWAIT(0);
        __syncthreads();
        u32 bb = sb + (c & 1)*OP_BUF;

        #pragma unroll
        for (int ks = 0; ks < 4; ks++) {
            u32 AF[2][4], BF[2][2];
            int ch = 2*ks + (mm >> 1);
            #pragma unroll
            for (int fm = 0; fm < 2; fm++) {
                int row = wm*32 + fm*16 + (mm & 1)*8 + mrl;
                u32 a = bb + row*128 + ((ch ^ (row & 7)) << 4);
                LDM4(AF[fm][0], AF[fm][1], AF[fm][2], AF[fm][3], a);
            }
            {
                int row = wn*16 + (mm & 1)*8 + mrl;
                u32 a = bb + 8192 + row*128 + ((ch ^ (row & 7)) << 4);
                LDM4(BF[0][0], BF[1][0], BF[0][1], BF[1][1], a);
            }
            #pragma unroll
            for (int fm = 0; fm < 2; fm++)
                #pragma unroll
                for (int fn = 0; fn < 2; fn++)
                    MMAH(C[fm][fn], AF[fm], BF[fn]);
        }
        __syncthreads();
        if (c + 2 < 8) OP_ISSUE(c + 2, c & 1);
    }

    #pragma unroll
    for (int fm = 0; fm < 2; fm++) {
        int rA = m0 + wm*32 + fm*16 + t8;
        #pragma unroll
        for (int fn = 0; fn < 2; fn++) {
            int n = n0 + wn*16 + fn*8 + 2*t4;
            *(float2*)(Yout + (size_t)rA*DIM + n) =
                make_float2(C[fm][fn][0]*INVWS, C[fm][fn][1]*INVWS);
            *(float2*)(Yout + (size_t)(rA+8)*DIM + n) =
                make_float2(C[fm][fn][2]*INVWS, C[fm][fn][3]*INVWS);
        }
    }
}

// ---------------- flash attention: 4 warps x 32 i-rows, HADD2 row sums ------
// K/V fragments read once per warp, used for 2 row-groups. 32 j-tiles of 64,
// 3 stages, 1 sync/iter. Row sums via HADD2 trees (ALU) + fp32 accumulation.
#define AT_STG 16384   // per stage: K 8KB @0, V 8KB @8192
__global__ __launch_bounds__(128, 2) void attn_kernel() {
    extern __shared__ char dsm[];
    u32 sb = (smem_u32(dsm) + 127) & ~127u;

    int tid = threadIdx.x, lane = tid & 31, warp = tid >> 5;   // warp 0..3
    int t4 = lane & 3, t8 = lane >> 2;
    int mrl = lane & 7, mm = lane >> 3;
    int i0 = blockIdx.x * 128;
    int bh = blockIdx.y, b = bh >> 3, hh = bh & 7;
    int combo = b*2 + (hh & 1);

    #define AT_ISSUE(jt, st) do { \
        _Pragma("unroll") \
        for (int q = 0; q < 8; q++) { \
            int idx = tid + q*128; \
            int mtx = idx >> 9, rem = idx & 511, r = rem >> 3, ch = rem & 7; \
            const __half* s = (mtx ? gV : gK) + (size_t)(b*SEQ + (jt)*64 + r)*DIM + hh*DK + ch*8; \
            u32 d = sb + (st)*AT_STG + mtx*8192 + r*128 + ((ch ^ (r & 7)) << 4); \
            CPA16(d, s); \
        } \
        CPCOMMIT(); \
    } while (0)

    AT_ISSUE(0, 0);
    AT_ISSUE(1, 1);

    // Q fragments (fp16): 2 groups of 16 rows, held for the whole kernel
    u32 QA[2][4][4];
    #pragma unroll
    for (int g = 0; g < 2; g++) {
        size_t qbase = (size_t)(b*SEQ + i0 + warp*32 + g*16 + t8)*DIM + hh*DK + 2*t4;
        #pragma unroll
        for (int ks = 0; ks < 4; ks++) {
            QA[g][ks][0] = *(const u32*)(gQ + qbase + ks*16);
            QA[g][ks][1] = *(const u32*)(gQ + qbase + ks*16 + 8*DIM);
            QA[g][ks][2] = *(const u32*)(gQ + qbase + ks*16 + 8);
            QA[g][ks][3] = *(const u32*)(gQ + qbase + ks*16 + 8*DIM + 8);
        }
    }

    const u32* mrowA0 = g_mask + ((size_t)combo*SEQ + i0 + warp*32 + t8)*(SEQ/32);
    const u32* mrowB0 = mrowA0 + 8*(SEQ/32);
    const u32* mrowA1 = mrowA0 + 16*(SEQ/32);
    const u32* mrowB1 = mrowA0 + 24*(SEQ/32);

    float O[2][8][4];
    #pragma unroll
    for (int g = 0; g < 2; g++)
        #pragma unroll
        for (int f = 0; f < 8; f++)
            #pragma unroll
            for (int c = 0; c < 4; c++) O[g][f][c] = 0.f;
    float lsA[2] = {0.f, 0.f}, lsB[2] = {0.f, 0.f};

    for (int t = 0; t < 32; t++) {
        if (t < 31) CPWAIT(1); else CPWAIT(0);
        __syncthreads();
        if (t + 2 < 32) AT_ISSUE(t + 2, (t + 2) % 3);
        u32 kb = sb + (t % 3)*AT_STG;
        u32 vb = kb + 8192;

        // mask words for both groups (LDG hidden under S MMAs); preshift 2*t4
        uint2 wA0 = *(const uint2*)(mrowA0 + (t << 1));
        uint2 wB0 = *(const uint2*)(mrowB0 + (t << 1));
        uint2 wA1 = *(const uint2*)(mrowA1 + (t << 1));
        uint2 wB1 = *(const uint2*)(mrowB1 + (t << 1));
        u64 sh = 2*t4;
        u64 A0 = ((u64)wA0.x | ((u64)wA0.y << 32)) >> sh;
        u64 B0 = ((u64)wB0.x | ((u64)wB0.y << 32)) >> sh;
        u64 A1 = ((u64)wA1.x | ((u64)wA1.y << 32)) >> sh;
        u64 B1 = ((u64)wB1.x | ((u64)wB1.y << 32)) >> sh;
        u32 aLo[2] = {(u32)A0, (u32)A1}, aHi[2] = {(u32)(A0 >> 32), (u32)(A1 >> 32)};
        u32 bLo[2] = {(u32)B0, (u32)B1}, bHi[2] = {(u32)(B0 >> 32), (u32)(B1 >> 32)};

        // S = Q K^T for both row-groups (K fragments loaded once)
        float S[2][8][4];
        #pragma unroll
        for (int g = 0; g < 2; g++)
            #pragma unroll
            for (int f = 0; f < 8; f++)
                #pragma unroll
                for (int c = 0; c < 4; c++) S[g][f][c] = 0.f;

        #pragma unroll
        for (int ks = 0; ks < 4; ks++) {
            u32 BH[8][2];
            int ch = 2*ks + (mm >> 1);
            #pragma unroll
            for (int p = 0; p < 4; p++) {
                int row = 16*p + (mm & 1)*8 + mrl;
                u32 a = kb + row*128 + ((ch ^ (row & 7)) << 4);
                LDM4(BH[2*p][0], BH[2*p+1][0], BH[2*p][1], BH[2*p+1][1], a);
            }
            #pragma unroll
            for (int g = 0; g < 2; g++)
                #pragma unroll
                for (int f = 0; f < 8; f++) MMAH(S[g][f], QA[g][ks], BH[f]);
        }

        // cvt to f16x2, LOP3 select -inf where masked, packed ex2
        u32 PH[2][4][4];
        #pragma unroll
        for (int g = 0; g < 2; g++)
            #pragma unroll
            for (int f = 0; f < 8; f++) {
                u32 uA = (f < 4 ? aLo[g] : aHi[g]) >> (8*(f & 3));
                u32 uB = (f < 4 ? bLo[g] : bHi[g]) >> (8*(f & 3));
                u32 r = ((uA << 7) & 0x80u) | ((uA << 14) & 0x8000u)
                      | ((uB << 23) & 0x800000u) | ((uB << 30) & 0x80000000u);
                u32 MA = prmt0(r, 0x9988u);
                u32 MB = prmt0(r, 0xBBAAu);
                u32 sA16 = cvtf16x2(S[g][f][0], S[g][f][1]);
                u32 sB16 = cvtf16x2(S[g][f][2], S[g][f][3]);
                u32 inA = (sA16 & MA) | (0xFC00FC00u & ~MA);
                u32 inB = (sB16 & MB) | (0xFC00FC00u & ~MB);
                int ks = f >> 1, o = (f & 1)*2;
                PH[g][ks][o]   = ex2h2(inA);
                PH[g][ks][o+1] = ex2h2(inB);
            }

        // row sums via HADD2 trees on the ALU pipe (idle), fp32 accumulate
        #pragma unroll
        for (int g = 0; g < 2; g++) {
            u32 sA = hadd2u(hadd2u(hadd2u(PH[g][0][0], PH[g][0][2]),
                                   hadd2u(PH[g][1][0], PH[g][1][2])),
                            hadd2u(hadd2u(PH[g][2][0], PH[g][2][2]),
                                   hadd2u(PH[g][3][0], PH[g][3][2])));
            u32 sB = hadd2u(hadd2u(hadd2u(PH[g][0][1], PH[g][0][3]),
                                   hadd2u(PH[g][1][1], PH[g][1][3])),
                            hadd2u(hadd2u(PH[g][2][1], PH[g][2][3]),
                                   hadd2u(PH[g][3][1], PH[g][3][3])));
            lsA[g] += h2sumf(sA);
            lsB[g] += h2sumf(sB);
        }

        // O += P V (V fragments loaded once per warp)
        #pragma unroll
        for (int ks = 0; ks < 4; ks++) {
            u32 VH[8][2];
            int row = 16*ks + (mm >> 1)*8 + mrl;
            #pragma unroll
            for (int p = 0; p < 4; p++) {
                int ch = 2*p + (mm & 1);
                u32 a = vb + row*128 + ((ch ^ (row & 7)) << 4);
                LDM4T(VH[2*p][0], VH[2*p+1][0], VH[2*p][1], VH[2*p+1][1], a);
            }
            #pragma unroll
            for (int g = 0; g < 2; g++)
                #pragma unroll
                for (int f = 0; f < 8; f++) MMAH(O[g][f], PH[g][ks], VH[f]);
        }
    }

    // reduce row sums across the 4 t4-lanes sharing each row
    #pragma unroll
    for (int g = 0; g < 2; g++) {
        lsA[g] += __shfl_xor_sync(0xffffffffu, lsA[g], 1);
        lsA[g] += __shfl_xor_sync(0xffffffffu, lsA[g], 2);
        lsB[g] += __shfl_xor_sync(0xffffffffu, lsB[g], 1);
        lsB[g] += __shfl_xor_sync(0xffffffffu, lsB[g], 2);
    }

    #pragma unroll
    for (int g = 0; g < 2; g++) {
        float invA = (lsA[g] > 0.f) ? 1.0f / lsA[g] : 0.f;
        float invB = (lsB[g] > 0.f) ? 1.0f / lsB[g] : 0.f;
        size_t obase = (size_t)(b*SEQ + i0 + warp*32 + g*16 + t8)*DIM + hh*DK + 2*t4;
        #pragma unroll
        for (int f = 0; f < 8; f++) {
            *(u32*)(gO + obase + 8*f)         = cvtf16x2(O[g][f][0]*invA, O[g][f][1]*invA);
            *(u32*)(gO + obase + 8*f + 8*DIM) = cvtf16x2(O[g][f][2]*invB, O[g][f][3]*invB);
        }
    }
}

// ---------------------------------------------------------------------------
extern "C" void kernel_launch(void* const* d_in, const int* in_sizes, int n_in,
                              void* d_out, int out_size)
{
    const float* x  = (const float*)d_in[0];
    const float* Wq = (const float*)d_in[1];
    const float* Wk = (const float*)d_in[2];
    const float* Wv = (const float*)d_in[3];
    const float* Wo = (const float*)d_in[4];
    const int* seq_mask     = (const int*)d_in[5];
    const int* sparse_masks = (const int*)d_in[6];
    float* out = (float*)d_out;

    cudaFuncSetAttribute(proj_gemm,   cudaFuncAttributeMaxDynamicSharedMemorySize, 2*PJ_BUF);
    cudaFuncSetAttribute(oproj_gemm,  cudaFuncAttributeMaxDynamicSharedMemorySize, 2*OP_BUF);
    cudaFuncSetAttribute(attn_kernel, cudaFuncAttributeMaxDynamicSharedMemorySize, 3*AT_STG);

    prep_all<<<5120, 256>>>(x, Wq, Wk, Wv, Wo, seq_mask, sparse_masks);

    proj_gemm<<<dim3(MT/64, 1536/128), 256, 2*PJ_BUF>>>();            // fused QKV
    attn_kernel<<<dim3(SEQ/128, BATCH*NHEAD), 128, 3*AT_STG>>>();
    oproj_gemm<<<dim3(MT/64, DIM/64), 256, 2*OP_BUF>>>(out);          // O @ Wo^T
    (void)in_sizes; (void)n_in; (void)out_size;
}